// round 2
// baseline (speedup 1.0000x reference)
#include <cuda_runtime.h>
#include <cuda_bf16.h>
#include <cstdint>

// Problem constants (fixed shapes)
#define NNODES 10000
#define NEDGES 640000
#define CIN    128
#define COUT   128
#define HDIM   256
#define BN_EPS 1e-5f

// ---------------------------------------------------------------------------
// Scratch (__device__ globals; no allocation allowed)
// ---------------------------------------------------------------------------
__device__ float g_AB[NNODES * 512];   // [n][0:256]=A'(dst term incl biases), [n][256:512]=B (src term)
__device__ float g_Wc[CIN * 512];      // BN-folded combined weight
__device__ float g_dv[512];            // combined bias
__device__ float g_W2t[HDIM * COUT];   // W2 rounded to tf32
__device__ int   g_is64;               // edge_index dtype flag
__device__ int   g_src[NEDGES];
__device__ int   g_dst[NEDGES];

// ---------------------------------------------------------------------------
// Helpers
// ---------------------------------------------------------------------------
__device__ __forceinline__ float tf32r(float x) {
    uint32_t u;
    asm("cvt.rna.tf32.f32 %0, %1;" : "=r"(u) : "f"(x));
    return __uint_as_float(u);
}

__device__ __forceinline__ void mma_tf32(float& c0, float& c1, float& c2, float& c3,
                                         float a0, float a1, float a2, float a3,
                                         float b0, float b1) {
    uint32_t ua0 = __float_as_uint(a0), ua1 = __float_as_uint(a1);
    uint32_t ua2 = __float_as_uint(a2), ua3 = __float_as_uint(a3);
    uint32_t ub0 = __float_as_uint(b0), ub1 = __float_as_uint(b1);
    asm volatile(
        "mma.sync.aligned.m16n8k8.row.col.f32.tf32.tf32.f32 "
        "{%0,%1,%2,%3}, {%4,%5,%6,%7}, {%8,%9}, {%0,%1,%2,%3};\n"
        : "+f"(c0), "+f"(c1), "+f"(c2), "+f"(c3)
        : "r"(ua0), "r"(ua1), "r"(ua2), "r"(ua3), "r"(ub0), "r"(ub1));
}

// ---------------------------------------------------------------------------
// Kernel A: detect edge_index dtype (int64 -> odd 32-bit words all zero)
// ---------------------------------------------------------------------------
__global__ void detect_kernel(const int* __restrict__ w) {
    __shared__ int acc;
    if (threadIdx.x == 0) acc = 0;
    __syncthreads();
    int v = 0;
    for (int i = threadIdx.x; i < 4096; i += blockDim.x) v |= w[2 * i + 1];
    atomicOr(&acc, v);
    __syncthreads();
    if (threadIdx.x == 0) g_is64 = (acc == 0) ? 1 : 0;
}

// ---------------------------------------------------------------------------
// Kernel B: extract src/dst as int32 (clamped) regardless of input dtype
// ---------------------------------------------------------------------------
__global__ void extract_kernel(const int* __restrict__ w) {
    int i = blockIdx.x * blockDim.x + threadIdx.x;
    if (i >= NEDGES) return;
    int s, d;
    if (g_is64) {
        s = w[2 * i];                    // low half of int64 src[i]
        d = w[2 * (NEDGES + i)];         // low half of int64 dst[i]
    } else {
        s = w[i];
        d = w[NEDGES + i];
    }
    g_src[i] = min(max(s, 0), NNODES - 1);
    g_dst[i] = min(max(d, 0), NNODES - 1);
}

// ---------------------------------------------------------------------------
// Kernel 0: prep — fold BN into W1, build combined weight/bias, round W2 to tf32
// ---------------------------------------------------------------------------
__global__ void prep_kernel(const float* __restrict__ gamma, const float* __restrict__ beta,
                            const float* __restrict__ mean, const float* __restrict__ var,
                            const float* __restrict__ W1, const float* __restrict__ b1,
                            const float* __restrict__ W2) {
    __shared__ float s_sh[CIN], t_sh[CIN];
    int j = threadIdx.x;  // 0..511
    if (j < CIN) {
        float s = gamma[j] * rsqrtf(var[j] + BN_EPS);
        s_sh[j] = s;
        t_sh[j] = beta[j] - mean[j] * s;
    }
    __syncthreads();

    float acc = 0.f;
    #pragma unroll 4
    for (int k = 0; k < CIN; ++k) {
        float wc;
        if (j < HDIM) wc = W1[k * HDIM + j] - W1[(k + CIN) * HDIM + j];   // W1top - W1bot
        else          wc = W1[(k + CIN) * HDIM + (j - HDIM)];             // W1bot
        g_Wc[k * 512 + j] = s_sh[k] * wc;
        acc += t_sh[k] * wc;
    }
    g_dv[j] = acc + ((j < HDIM) ? b1[j] : 0.f);

    for (int idx = j; idx < HDIM * COUT; idx += 512)
        g_W2t[idx] = tf32r(W2[idx]);
}

// ---------------------------------------------------------------------------
// Kernel 1: zero output
// ---------------------------------------------------------------------------
__global__ void zero_kernel(float* __restrict__ out, int n) {
    int i = blockIdx.x * blockDim.x + threadIdx.x;
    if (i < n) out[i] = 0.f;
}

// ---------------------------------------------------------------------------
// Kernel 2: node GEMM  AB[10000,512] = x[10000,128] @ g_Wc[128,512] + g_dv
// ---------------------------------------------------------------------------
__global__ __launch_bounds__(256) void gemm_nodes_kernel(const float* __restrict__ x) {
    __shared__ float As[16][64];   // [k][m]
    __shared__ float Bs[16][64];   // [k][n]
    int tid = threadIdx.x;
    int m0 = blockIdx.x * 64, n0 = blockIdx.y * 64;
    int tx = tid & 15, ty = tid >> 4;

    int lr = tid >> 2;           // A-load row (0..63)
    int lc = (tid & 3) * 4;      // A-load k
    int br = tid >> 4;           // B-load k
    int bc = (tid & 15) * 4;     // B-load n

    float acc[4][4];
    #pragma unroll
    for (int i = 0; i < 4; ++i)
        #pragma unroll
        for (int jq = 0; jq < 4; ++jq) acc[i][jq] = 0.f;

    for (int k0 = 0; k0 < CIN; k0 += 16) {
        float4 av = make_float4(0.f, 0.f, 0.f, 0.f);
        int row = m0 + lr;
        if (row < NNODES) av = *(const float4*)(x + row * CIN + k0 + lc);
        As[lc + 0][lr] = av.x; As[lc + 1][lr] = av.y;
        As[lc + 2][lr] = av.z; As[lc + 3][lr] = av.w;

        float4 bv = *(const float4*)(g_Wc + (k0 + br) * 512 + n0 + bc);
        *(float4*)&Bs[br][bc] = bv;
        __syncthreads();

        #pragma unroll
        for (int k = 0; k < 16; ++k) {
            float4 a = *(const float4*)&As[k][ty * 4];
            float4 b = *(const float4*)&Bs[k][tx * 4];
            float ar[4] = {a.x, a.y, a.z, a.w};
            float bw[4] = {b.x, b.y, b.z, b.w};
            #pragma unroll
            for (int i = 0; i < 4; ++i)
                #pragma unroll
                for (int jq = 0; jq < 4; ++jq)
                    acc[i][jq] = fmaf(ar[i], bw[jq], acc[i][jq]);
        }
        __syncthreads();
    }

    float4 dv4 = *(const float4*)(g_dv + n0 + tx * 4);
    #pragma unroll
    for (int i = 0; i < 4; ++i) {
        int row = m0 + ty * 4 + i;
        if (row < NNODES) {
            float4 o;
            o.x = acc[i][0] + dv4.x; o.y = acc[i][1] + dv4.y;
            o.z = acc[i][2] + dv4.z; o.w = acc[i][3] + dv4.w;
            *(float4*)(g_AB + row * 512 + n0 + tx * 4) = o;
        }
    }
}

// ---------------------------------------------------------------------------
// Kernel 3: persistent edge kernel
// ---------------------------------------------------------------------------
#define TILE_E 64
#define HS 260          // h_s row stride (words)
#define WS 136          // W2_s row stride (words)
#define NTILES (NEDGES / TILE_E)   // 10000 exactly

#define SMEM_W2 (HDIM * WS)        // 34816 floats
#define SMEM_H  (TILE_E * HS)      // 16640 floats
#define SMEM_FLOATS (SMEM_W2 + SMEM_H + COUT)
#define SMEM_BYTES  (SMEM_FLOATS * 4 + 2 * TILE_E * 4)

__global__ __launch_bounds__(256) void edge_kernel(const float* __restrict__ b2,
                                                   int* __restrict__ outI) {
    extern __shared__ float smem[];
    float* W2_s = smem;                    // [256][WS]
    float* h_s  = W2_s + SMEM_W2;          // [64][HS]
    float* b2_s = h_s + SMEM_H;            // [128]
    int*   dst_s = (int*)(b2_s + COUT);    // [64]
    int*   src_s = dst_s + TILE_E;         // [64]

    const int tid  = threadIdx.x;
    const int lane = tid & 31;
    const int w    = tid >> 5;
    const int wm   = w & 1;                // m-tile of 32 rows
    const int wn   = w >> 1;               // n-tile of 32 cols
    const int g    = lane >> 2;            // 0..7
    const int tg   = lane & 3;             // 0..3

    for (int idx = tid; idx < HDIM * COUT; idx += 256) {
        int k = idx >> 7, n = idx & 127;
        W2_s[k * WS + n] = g_W2t[idx];
    }
    if (tid < COUT) b2_s[tid] = b2[tid];

    for (int tile = blockIdx.x; tile < NTILES; tile += gridDim.x) {
        __syncthreads();

        if (tid < TILE_E) {
            int e = tile * TILE_E + tid;
            src_s[tid] = g_src[e];
            dst_s[tid] = g_dst[e];
        }
        __syncthreads();

        // Stage 1: gather + relu + tf32-round into h_s. thread == feature t.
        #pragma unroll 4
        for (int m = 0; m < TILE_E; ++m) {
            int d = dst_s[m], s = src_s[m];
            float va = g_AB[d * 512 + tid];          // A'[dst][t]
            float vb = g_AB[s * 512 + 256 + tid];    // B[src][t]
            h_s[m * HS + tid] = tf32r(fmaxf(va + vb, 0.f));
        }
        __syncthreads();

        // Stage 2: warp-level tf32 mma: [64x256] @ [256x128]
        float acc[2][4][4];
        #pragma unroll
        for (int mt = 0; mt < 2; ++mt)
            #pragma unroll
            for (int nt = 0; nt < 4; ++nt)
                #pragma unroll
                for (int i = 0; i < 4; ++i) acc[mt][nt][i] = 0.f;

        #pragma unroll 4
        for (int ks = 0; ks < HDIM / 8; ++ks) {
            int k0 = ks * 8;
            float a[2][4];
            #pragma unroll
            for (int mt = 0; mt < 2; ++mt) {
                int base = (wm * 32 + mt * 16 + g) * HS + k0 + tg;
                a[mt][0] = h_s[base];
                a[mt][1] = h_s[base + 8 * HS];
                a[mt][2] = h_s[base + 4];
                a[mt][3] = h_s[base + 8 * HS + 4];
            }
            float b[4][2];
            #pragma unroll
            for (int nt = 0; nt < 4; ++nt) {
                int bn = wn * 32 + nt * 8 + g;
                b[nt][0] = W2_s[(k0 + tg) * WS + bn];
                b[nt][1] = W2_s[(k0 + tg + 4) * WS + bn];
            }
            #pragma unroll
            for (int mt = 0; mt < 2; ++mt)
                #pragma unroll
                for (int nt = 0; nt < 4; ++nt)
                    mma_tf32(acc[mt][nt][0], acc[mt][nt][1], acc[mt][nt][2], acc[mt][nt][3],
                             a[mt][0], a[mt][1], a[mt][2], a[mt][3],
                             b[nt][0], b[nt][1]);
        }

        // Epilogue: +b2, predicated int atomicMax (positive values only)
        #pragma unroll
        for (int mt = 0; mt < 2; ++mt) {
            #pragma unroll
            for (int nt = 0; nt < 4; ++nt) {
                #pragma unroll
                for (int i = 0; i < 4; ++i) {
                    int rowm = wm * 32 + mt * 16 + g + ((i >> 1) * 8);
                    int col  = wn * 32 + nt * 8 + tg * 2 + (i & 1);
                    float v = acc[mt][nt][i] + b2_s[col];
                    if (v > 0.f) {
                        int d = dst_s[rowm];
                        atomicMax(outI + d * COUT + col, __float_as_int(v));
                    }
                }
            }
        }
    }
}

// ---------------------------------------------------------------------------
// Launch
// ---------------------------------------------------------------------------
extern "C" void kernel_launch(void* const* d_in, const int* in_sizes, int n_in,
                              void* d_out, int out_size) {
    const float* x        = (const float*)d_in[0];
    const int*   eiw      = (const int*)d_in[1];   // raw words; dtype detected on device
    const float* bn_gamma = (const float*)d_in[2];
    const float* bn_beta  = (const float*)d_in[3];
    const float* bn_mean  = (const float*)d_in[4];
    const float* bn_var   = (const float*)d_in[5];
    const float* W1       = (const float*)d_in[6];
    const float* b1       = (const float*)d_in[7];
    const float* W2       = (const float*)d_in[8];
    const float* b2       = (const float*)d_in[9];
    float* out = (float*)d_out;

    cudaFuncSetAttribute(edge_kernel, cudaFuncAttributeMaxDynamicSharedMemorySize, SMEM_BYTES);

    detect_kernel<<<1, 256>>>(eiw);
    extract_kernel<<<(NEDGES + 255) / 256, 256>>>(eiw);
    prep_kernel<<<1, 512>>>(bn_gamma, bn_beta, bn_mean, bn_var, W1, b1, W2);
    zero_kernel<<<(NNODES * COUT + 511) / 512, 512>>>(out, NNODES * COUT);
    dim3 g1((NNODES + 63) / 64, 512 / 64);
    gemm_nodes_kernel<<<g1, 256>>>(x);
    edge_kernel<<<152, 256, SMEM_BYTES>>>(b2, (int*)d_out);
}

// round 3
// speedup vs baseline: 2.7707x; 2.7707x over previous
#include <cuda_runtime.h>
#include <cuda_fp16.h>
#include <cstdint>

// Problem constants (fixed shapes)
#define NNODES 10000
#define NEDGES 640000
#define CIN    128
#define COUT   128
#define HDIM   256
#define BN_EPS 1e-5f

// ---------------------------------------------------------------------------
// Scratch (__device__ globals; no allocation allowed)
// ---------------------------------------------------------------------------
__device__ float g_AB[NNODES * 512];    // [n][0:256]=A'(dst term incl biases), [n][256:512]=B (src term)
__device__ float g_Wc[CIN * 512];       // BN-folded combined weight
__device__ float g_dv[512];             // combined bias
__device__ __half g_W2h[COUT * HDIM];   // W2 transposed [n][k], fp16
__device__ int   g_is64;
__device__ int   g_src[NEDGES];
__device__ int   g_dst[NEDGES];

// ---------------------------------------------------------------------------
// fp16 mma m16n8k16, fp32 accumulate
// ---------------------------------------------------------------------------
__device__ __forceinline__ void mma_f16(float& c0, float& c1, float& c2, float& c3,
                                        uint32_t a0, uint32_t a1, uint32_t a2, uint32_t a3,
                                        uint32_t b0, uint32_t b1) {
    asm volatile(
        "mma.sync.aligned.m16n8k16.row.col.f32.f16.f16.f32 "
        "{%0,%1,%2,%3}, {%4,%5,%6,%7}, {%8,%9}, {%0,%1,%2,%3};\n"
        : "+f"(c0), "+f"(c1), "+f"(c2), "+f"(c3)
        : "r"(a0), "r"(a1), "r"(a2), "r"(a3), "r"(b0), "r"(b1));
}

// ---------------------------------------------------------------------------
// Kernel A: detect edge_index dtype (int64 -> odd 32-bit words all zero)
// ---------------------------------------------------------------------------
__global__ void detect_kernel(const int* __restrict__ w) {
    __shared__ int acc;
    if (threadIdx.x == 0) acc = 0;
    __syncthreads();
    int v = 0;
    for (int i = threadIdx.x; i < 4096; i += blockDim.x) v |= w[2 * i + 1];
    atomicOr(&acc, v);
    __syncthreads();
    if (threadIdx.x == 0) g_is64 = (acc == 0) ? 1 : 0;
}

// ---------------------------------------------------------------------------
// Kernel B: extract src/dst as int32 (clamped)
// ---------------------------------------------------------------------------
__global__ void extract_kernel(const int* __restrict__ w) {
    int i = blockIdx.x * blockDim.x + threadIdx.x;
    if (i >= NEDGES) return;
    int s, d;
    if (g_is64) {
        s = w[2 * i];
        d = w[2 * (NEDGES + i)];
    } else {
        s = w[i];
        d = w[NEDGES + i];
    }
    g_src[i] = min(max(s, 0), NNODES - 1);
    g_dst[i] = min(max(d, 0), NNODES - 1);
}

// ---------------------------------------------------------------------------
// Kernel 0: prep — fold BN into W1, build combined weight/bias, W2^T fp16
// ---------------------------------------------------------------------------
__global__ void prep_kernel(const float* __restrict__ gamma, const float* __restrict__ beta,
                            const float* __restrict__ mean, const float* __restrict__ var,
                            const float* __restrict__ W1, const float* __restrict__ b1,
                            const float* __restrict__ W2) {
    __shared__ float s_sh[CIN], t_sh[CIN];
    int j = threadIdx.x;  // 0..511
    if (j < CIN) {
        float s = gamma[j] * rsqrtf(var[j] + BN_EPS);
        s_sh[j] = s;
        t_sh[j] = beta[j] - mean[j] * s;
    }
    __syncthreads();

    float acc = 0.f;
    #pragma unroll 4
    for (int k = 0; k < CIN; ++k) {
        float wc;
        if (j < HDIM) wc = W1[k * HDIM + j] - W1[(k + CIN) * HDIM + j];   // W1top - W1bot
        else          wc = W1[(k + CIN) * HDIM + (j - HDIM)];             // W1bot
        g_Wc[k * 512 + j] = s_sh[k] * wc;
        acc += t_sh[k] * wc;
    }
    g_dv[j] = acc + ((j < HDIM) ? b1[j] : 0.f);

    // W2 transposed to [n][k], fp16
    for (int idx = j; idx < COUT * HDIM; idx += 512) {
        int n = idx >> 8, k = idx & 255;
        g_W2h[idx] = __float2half_rn(W2[k * COUT + n]);
    }
}

// ---------------------------------------------------------------------------
// Kernel 1: zero output
// ---------------------------------------------------------------------------
__global__ void zero_kernel(float* __restrict__ out, int n) {
    int i = blockIdx.x * blockDim.x + threadIdx.x;
    if (i < n) out[i] = 0.f;
}

// ---------------------------------------------------------------------------
// Kernel 2: node GEMM  AB[10000,512] = x[10000,128] @ g_Wc[128,512] + g_dv
// ---------------------------------------------------------------------------
__global__ __launch_bounds__(256) void gemm_nodes_kernel(const float* __restrict__ x) {
    __shared__ float As[16][64];
    __shared__ float Bs[16][64];
    int tid = threadIdx.x;
    int m0 = blockIdx.x * 64, n0 = blockIdx.y * 64;
    int tx = tid & 15, ty = tid >> 4;

    int lr = tid >> 2;
    int lc = (tid & 3) * 4;
    int br = tid >> 4;
    int bc = (tid & 15) * 4;

    float acc[4][4];
    #pragma unroll
    for (int i = 0; i < 4; ++i)
        #pragma unroll
        for (int jq = 0; jq < 4; ++jq) acc[i][jq] = 0.f;

    for (int k0 = 0; k0 < CIN; k0 += 16) {
        float4 av = make_float4(0.f, 0.f, 0.f, 0.f);
        int row = m0 + lr;
        if (row < NNODES) av = *(const float4*)(x + row * CIN + k0 + lc);
        As[lc + 0][lr] = av.x; As[lc + 1][lr] = av.y;
        As[lc + 2][lr] = av.z; As[lc + 3][lr] = av.w;

        float4 bv = *(const float4*)(g_Wc + (k0 + br) * 512 + n0 + bc);
        *(float4*)&Bs[br][bc] = bv;
        __syncthreads();

        #pragma unroll
        for (int k = 0; k < 16; ++k) {
            float4 a = *(const float4*)&As[k][ty * 4];
            float4 b = *(const float4*)&Bs[k][tx * 4];
            float ar[4] = {a.x, a.y, a.z, a.w};
            float bw[4] = {b.x, b.y, b.z, b.w};
            #pragma unroll
            for (int i = 0; i < 4; ++i)
                #pragma unroll
                for (int jq = 0; jq < 4; ++jq)
                    acc[i][jq] = fmaf(ar[i], bw[jq], acc[i][jq]);
        }
        __syncthreads();
    }

    float4 dv4 = *(const float4*)(g_dv + n0 + tx * 4);
    #pragma unroll
    for (int i = 0; i < 4; ++i) {
        int row = m0 + ty * 4 + i;
        if (row < NNODES) {
            float4 o;
            o.x = acc[i][0] + dv4.x; o.y = acc[i][1] + dv4.y;
            o.z = acc[i][2] + dv4.z; o.w = acc[i][3] + dv4.w;
            *(float4*)(g_AB + row * 512 + n0 + tx * 4) = o;
        }
    }
}

// ---------------------------------------------------------------------------
// Kernel 3: persistent edge kernel (fp16 mma, 2 CTAs/SM)
// ---------------------------------------------------------------------------
#define TILE_E 64
#define KS 264                      // half stride per row (132 words; %32==4 -> conflict-free)
#define NTILES (NEDGES / TILE_E)    // 10000

#define SMEM_W2_HALVES (COUT * KS)    // 33792 halves
#define SMEM_H_HALVES  (TILE_E * KS)  // 16896 halves
#define SMEM_BYTES ((SMEM_W2_HALVES + SMEM_H_HALVES) * 2 + COUT * 4 + 2 * TILE_E * 4)

__global__ __launch_bounds__(256, 2) void edge_kernel(const float* __restrict__ b2,
                                                      int* __restrict__ outI) {
    extern __shared__ __half smem[];
    __half* W2_s = smem;                         // [128][KS] (n-major, transposed W2)
    __half* h_s  = W2_s + SMEM_W2_HALVES;        // [64][KS]
    float*  b2_s = (float*)(h_s + SMEM_H_HALVES);// [128]
    int*    dst_s = (int*)(b2_s + COUT);         // [64]
    int*    src_s = dst_s + TILE_E;              // [64]

    const int tid  = threadIdx.x;
    const int lane = tid & 31;
    const int w    = tid >> 5;
    const int wm   = w & 1;                // 32-row block
    const int wn   = w >> 1;               // 32-col block
    const int g    = lane >> 2;            // 0..7
    const int tg   = lane & 3;             // 0..3

    // Load W2^T (fp16) into smem as half2 words
    for (int idx = tid; idx < COUT * HDIM / 2; idx += 256) {
        int n = idx >> 7, kw = idx & 127;
        *(uint32_t*)&W2_s[n * KS + 2 * kw] = ((const uint32_t*)g_W2h)[idx];
    }
    if (tid < COUT) b2_s[tid] = b2[tid];

    const int half_id = tid >> 7;         // 0 or 1: which of the 2 rows per iter
    const int feat    = (tid & 127) * 2;  // feature pair

    for (int tile = blockIdx.x; tile < NTILES; tile += gridDim.x) {
        __syncthreads();

        if (tid < TILE_E) {
            int e = tile * TILE_E + tid;
            src_s[tid] = g_src[e];
            dst_s[tid] = g_dst[e];
        }
        __syncthreads();

        // Stage 1: gather + relu -> fp16 h_s. 128 threads per row, 2 rows at once.
        #pragma unroll 8
        for (int m0 = 0; m0 < TILE_E; m0 += 2) {
            int row = m0 + half_id;
            int d = dst_s[row], s = src_s[row];
            float2 va = *(const float2*)&g_AB[d * 512 + feat];
            float2 vb = *(const float2*)&g_AB[s * 512 + 256 + feat];
            float h0 = fmaxf(va.x + vb.x, 0.f);
            float h1 = fmaxf(va.y + vb.y, 0.f);
            *(__half2*)&h_s[row * KS + feat] = __floats2half2_rn(h0, h1);
        }
        __syncthreads();

        // Stage 2: fp16 mma [64x256] @ [256x128] (W2 stored [n][k])
        float acc[2][4][4];
        #pragma unroll
        for (int mt = 0; mt < 2; ++mt)
            #pragma unroll
            for (int nt = 0; nt < 4; ++nt)
                #pragma unroll
                for (int i = 0; i < 4; ++i) acc[mt][nt][i] = 0.f;

        #pragma unroll 4
        for (int ks = 0; ks < HDIM / 16; ++ks) {
            int k0 = ks * 16;
            uint32_t a[2][4];
            #pragma unroll
            for (int mt = 0; mt < 2; ++mt) {
                int mrow = wm * 32 + mt * 16 + g;
                const __half* base = h_s + mrow * KS + k0 + 2 * tg;
                a[mt][0] = *(const uint32_t*)(base);
                a[mt][1] = *(const uint32_t*)(base + 8 * KS);
                a[mt][2] = *(const uint32_t*)(base + 8);
                a[mt][3] = *(const uint32_t*)(base + 8 * KS + 8);
            }
            uint32_t b[4][2];
            #pragma unroll
            for (int nt = 0; nt < 4; ++nt) {
                int bn = wn * 32 + nt * 8 + g;
                const __half* base = W2_s + bn * KS + k0 + 2 * tg;
                b[nt][0] = *(const uint32_t*)(base);
                b[nt][1] = *(const uint32_t*)(base + 8);
            }
            #pragma unroll
            for (int mt = 0; mt < 2; ++mt)
                #pragma unroll
                for (int nt = 0; nt < 4; ++nt)
                    mma_f16(acc[mt][nt][0], acc[mt][nt][1], acc[mt][nt][2], acc[mt][nt][3],
                            a[mt][0], a[mt][1], a[mt][2], a[mt][3],
                            b[nt][0], b[nt][1]);
        }

        // Epilogue: +b2, predicated positive-only int atomicMax
        #pragma unroll
        for (int mt = 0; mt < 2; ++mt) {
            #pragma unroll
            for (int nt = 0; nt < 4; ++nt) {
                #pragma unroll
                for (int i = 0; i < 4; ++i) {
                    int rowm = wm * 32 + mt * 16 + g + ((i >> 1) * 8);
                    int col  = wn * 32 + nt * 8 + tg * 2 + (i & 1);
                    float v = acc[mt][nt][i] + b2_s[col];
                    if (v > 0.f) {
                        int d = dst_s[rowm];
                        atomicMax(outI + d * COUT + col, __float_as_int(v));
                    }
                }
            }
        }
    }
}

// ---------------------------------------------------------------------------
// Launch
// ---------------------------------------------------------------------------
extern "C" void kernel_launch(void* const* d_in, const int* in_sizes, int n_in,
                              void* d_out, int out_size) {
    const float* x        = (const float*)d_in[0];
    const int*   eiw      = (const int*)d_in[1];
    const float* bn_gamma = (const float*)d_in[2];
    const float* bn_beta  = (const float*)d_in[3];
    const float* bn_mean  = (const float*)d_in[4];
    const float* bn_var   = (const float*)d_in[5];
    const float* W1       = (const float*)d_in[6];
    const float* b1       = (const float*)d_in[7];
    const float* W2       = (const float*)d_in[8];
    const float* b2       = (const float*)d_in[9];
    float* out = (float*)d_out;

    cudaFuncSetAttribute(edge_kernel, cudaFuncAttributeMaxDynamicSharedMemorySize, SMEM_BYTES);

    detect_kernel<<<1, 256>>>(eiw);
    extract_kernel<<<(NEDGES + 255) / 256, 256>>>(eiw);
    prep_kernel<<<1, 512>>>(bn_gamma, bn_beta, bn_mean, bn_var, W1, b1, W2);
    zero_kernel<<<(NNODES * COUT + 511) / 512, 512>>>(out, NNODES * COUT);
    dim3 g1((NNODES + 63) / 64, 512 / 64);
    gemm_nodes_kernel<<<g1, 256>>>(x);
    edge_kernel<<<304, 256, SMEM_BYTES>>>(b2, (int*)d_out);
}

// round 4
// speedup vs baseline: 3.6410x; 1.3141x over previous
#include <cuda_runtime.h>
#include <cuda_fp16.h>
#include <cstdint>

// Problem constants (fixed shapes)
#define NNODES 10000
#define NEDGES 640000
#define CIN    128
#define COUT   128
#define HDIM   256
#define BN_EPS 1e-5f

// ---------------------------------------------------------------------------
// Scratch (__device__ globals; no allocation allowed)
// ---------------------------------------------------------------------------
__device__ __half g_ABh[NNODES * 512];  // fp16: [n][0:256]=A'(dst term incl biases), [n][256:512]=B (src term)
__device__ float  g_Wc[CIN * 512];      // BN-folded combined weight
__device__ float  g_dv[512];            // combined bias
__device__ __half g_W2h[COUT * HDIM];   // W2 transposed [n][k], fp16
__device__ int    g_is64;
__device__ int    g_src[NEDGES];
__device__ int    g_dst[NEDGES];

// ---------------------------------------------------------------------------
// fp16 mma m16n8k16, fp32 accumulate
// ---------------------------------------------------------------------------
__device__ __forceinline__ void mma_f16(float& c0, float& c1, float& c2, float& c3,
                                        uint32_t a0, uint32_t a1, uint32_t a2, uint32_t a3,
                                        uint32_t b0, uint32_t b1) {
    asm volatile(
        "mma.sync.aligned.m16n8k16.row.col.f32.f16.f16.f32 "
        "{%0,%1,%2,%3}, {%4,%5,%6,%7}, {%8,%9}, {%0,%1,%2,%3};\n"
        : "+f"(c0), "+f"(c1), "+f"(c2), "+f"(c3)
        : "r"(a0), "r"(a1), "r"(a2), "r"(a3), "r"(b0), "r"(b1));
}

__device__ __forceinline__ void ldsm_x4(uint32_t& r0, uint32_t& r1, uint32_t& r2, uint32_t& r3,
                                        uint32_t addr) {
    asm volatile("ldmatrix.sync.aligned.m8n8.x4.shared.b16 {%0,%1,%2,%3}, [%4];"
                 : "=r"(r0), "=r"(r1), "=r"(r2), "=r"(r3) : "r"(addr));
}

// ---------------------------------------------------------------------------
// Kernel A: detect edge_index dtype (int64 -> odd 32-bit words all zero)
// ---------------------------------------------------------------------------
__global__ void detect_kernel(const int* __restrict__ w) {
    __shared__ int acc;
    if (threadIdx.x == 0) acc = 0;
    __syncthreads();
    int v = 0;
    for (int i = threadIdx.x; i < 4096; i += blockDim.x) v |= w[2 * i + 1];
    atomicOr(&acc, v);
    __syncthreads();
    if (threadIdx.x == 0) g_is64 = (acc == 0) ? 1 : 0;
}

// ---------------------------------------------------------------------------
// Kernel B: extract src/dst as int32 (clamped)
// ---------------------------------------------------------------------------
__global__ void extract_kernel(const int* __restrict__ w) {
    int i = blockIdx.x * blockDim.x + threadIdx.x;
    if (i >= NEDGES) return;
    int s, d;
    if (g_is64) {
        s = w[2 * i];
        d = w[2 * (NEDGES + i)];
    } else {
        s = w[i];
        d = w[NEDGES + i];
    }
    g_src[i] = min(max(s, 0), NNODES - 1);
    g_dst[i] = min(max(d, 0), NNODES - 1);
}

// ---------------------------------------------------------------------------
// Kernel 0: prep — fold BN into W1, build combined weight/bias, W2^T fp16
// ---------------------------------------------------------------------------
__global__ void prep_kernel(const float* __restrict__ gamma, const float* __restrict__ beta,
                            const float* __restrict__ mean, const float* __restrict__ var,
                            const float* __restrict__ W1, const float* __restrict__ b1,
                            const float* __restrict__ W2) {
    __shared__ float s_sh[CIN], t_sh[CIN];
    int j = threadIdx.x;  // 0..511
    if (j < CIN) {
        float s = gamma[j] * rsqrtf(var[j] + BN_EPS);
        s_sh[j] = s;
        t_sh[j] = beta[j] - mean[j] * s;
    }
    __syncthreads();

    float acc = 0.f;
    #pragma unroll 4
    for (int k = 0; k < CIN; ++k) {
        float wc;
        if (j < HDIM) wc = W1[k * HDIM + j] - W1[(k + CIN) * HDIM + j];   // W1top - W1bot
        else          wc = W1[(k + CIN) * HDIM + (j - HDIM)];             // W1bot
        g_Wc[k * 512 + j] = s_sh[k] * wc;
        acc += t_sh[k] * wc;
    }
    g_dv[j] = acc + ((j < HDIM) ? b1[j] : 0.f);

    // W2 transposed to [n][k], fp16
    for (int idx = j; idx < COUT * HDIM; idx += 512) {
        int n = idx >> 8, k = idx & 255;
        g_W2h[idx] = __float2half_rn(W2[k * COUT + n]);
    }
}

// ---------------------------------------------------------------------------
// Kernel 1: zero output
// ---------------------------------------------------------------------------
__global__ void zero_kernel(float* __restrict__ out, int n) {
    int i = blockIdx.x * blockDim.x + threadIdx.x;
    if (i < n) out[i] = 0.f;
}

// ---------------------------------------------------------------------------
// Kernel 2: node GEMM  AB[10000,512] = x[10000,128] @ g_Wc[128,512] + g_dv
// Output stored fp16.
// ---------------------------------------------------------------------------
__global__ __launch_bounds__(256) void gemm_nodes_kernel(const float* __restrict__ x) {
    __shared__ float As[16][64];
    __shared__ float Bs[16][64];
    int tid = threadIdx.x;
    int m0 = blockIdx.x * 64, n0 = blockIdx.y * 64;
    int tx = tid & 15, ty = tid >> 4;

    int lr = tid >> 2;
    int lc = (tid & 3) * 4;
    int br = tid >> 4;
    int bc = (tid & 15) * 4;

    float acc[4][4];
    #pragma unroll
    for (int i = 0; i < 4; ++i)
        #pragma unroll
        for (int jq = 0; jq < 4; ++jq) acc[i][jq] = 0.f;

    for (int k0 = 0; k0 < CIN; k0 += 16) {
        float4 av = make_float4(0.f, 0.f, 0.f, 0.f);
        int row = m0 + lr;
        if (row < NNODES) av = *(const float4*)(x + row * CIN + k0 + lc);
        As[lc + 0][lr] = av.x; As[lc + 1][lr] = av.y;
        As[lc + 2][lr] = av.z; As[lc + 3][lr] = av.w;

        float4 bv = *(const float4*)(g_Wc + (k0 + br) * 512 + n0 + bc);
        *(float4*)&Bs[br][bc] = bv;
        __syncthreads();

        #pragma unroll
        for (int k = 0; k < 16; ++k) {
            float4 a = *(const float4*)&As[k][ty * 4];
            float4 b = *(const float4*)&Bs[k][tx * 4];
            float ar[4] = {a.x, a.y, a.z, a.w};
            float bw[4] = {b.x, b.y, b.z, b.w};
            #pragma unroll
            for (int i = 0; i < 4; ++i)
                #pragma unroll
                for (int jq = 0; jq < 4; ++jq)
                    acc[i][jq] = fmaf(ar[i], bw[jq], acc[i][jq]);
        }
        __syncthreads();
    }

    float4 dv4 = *(const float4*)(g_dv + n0 + tx * 4);
    #pragma unroll
    for (int i = 0; i < 4; ++i) {
        int row = m0 + ty * 4 + i;
        if (row < NNODES) {
            __half2 h0 = __floats2half2_rn(acc[i][0] + dv4.x, acc[i][1] + dv4.y);
            __half2 h1 = __floats2half2_rn(acc[i][2] + dv4.z, acc[i][3] + dv4.w);
            uint2 o;
            o.x = *(uint32_t*)&h0;
            o.y = *(uint32_t*)&h1;
            *(uint2*)&g_ABh[row * 512 + n0 + tx * 4] = o;
        }
    }
}

// ---------------------------------------------------------------------------
// Kernel 3: persistent edge kernel (fp16 gather + ldmatrix + fp16 mma, 2 CTAs/SM)
// ---------------------------------------------------------------------------
#define TILE_E 64
#define KS 264                      // half stride per row (132 words; %32==4 -> conflict-free)
#define NTILES (NEDGES / TILE_E)    // 10000

#define SMEM_W2_HALVES (COUT * KS)    // 33792 halves
#define SMEM_H_HALVES  (TILE_E * KS)  // 16896 halves
#define SMEM_BYTES ((SMEM_W2_HALVES + SMEM_H_HALVES) * 2 + COUT * 4 + 2 * TILE_E * 4)

__global__ __launch_bounds__(256, 2) void edge_kernel(const float* __restrict__ b2,
                                                      int* __restrict__ outI) {
    extern __shared__ __half smem[];
    __half* W2_s = smem;                          // [128][KS]
    __half* h_s  = W2_s + SMEM_W2_HALVES;         // [64][KS]
    float*  b2_s = (float*)(h_s + SMEM_H_HALVES); // [128]
    int*    dst_s = (int*)(b2_s + COUT);          // [64]
    int*    src_s = dst_s + TILE_E;               // [64]

    const int tid  = threadIdx.x;
    const int lane = tid & 31;
    const int w    = tid >> 5;
    const int wm   = w & 1;                // 32-row block
    const int wn   = w >> 1;               // 32-col block
    const int g    = lane >> 2;            // 0..7
    const int tg   = lane & 3;             // 0..3

    // Load W2^T (fp16) into smem
    for (int idx = tid; idx < COUT * HDIM / 2; idx += 256) {
        int n = idx >> 7, kw = idx & 127;
        *(uint32_t*)&W2_s[n * KS + 2 * kw] = ((const uint32_t*)g_W2h)[idx];
    }
    if (tid < COUT) b2_s[tid] = b2[tid];

    // ldmatrix per-lane base addresses
    const uint32_t h_addr  = (uint32_t)__cvta_generic_to_shared(h_s);
    const uint32_t w2_addr = (uint32_t)__cvta_generic_to_shared(W2_s);
    const int mat = lane >> 3, r8 = lane & 7;
    uint32_t aBase[2], bBase[2];
    #pragma unroll
    for (int mt = 0; mt < 2; ++mt) {
        int row = wm * 32 + mt * 16 + (mat & 1) * 8 + r8;
        aBase[mt] = h_addr + (row * KS + (mat >> 1) * 8) * 2;
    }
    #pragma unroll
    for (int p = 0; p < 2; ++p) {
        int n = wn * 32 + p * 16 + (mat >> 1) * 8 + r8;
        bBase[p] = w2_addr + (n * KS + (mat & 1) * 8) * 2;
    }

    const int rsel = tid >> 6;         // 0..3 (row within 4-row group)
    const int c4   = (tid & 63) * 4;   // half offset within row

    for (int tile = blockIdx.x; tile < NTILES; tile += gridDim.x) {
        __syncthreads();

        if (tid < TILE_E) {
            int e = tile * TILE_E + tid;
            src_s[tid] = g_src[e];
            dst_s[tid] = g_dst[e];
        }
        __syncthreads();

        // Stage 1: fp16 gather + relu -> h_s. 64 threads per row, 4 rows per iter.
        const __half2 z2 = __float2half2_rn(0.f);
        #pragma unroll 8
        for (int m0 = 0; m0 < TILE_E; m0 += 4) {
            int row = m0 + rsel;
            int d = dst_s[row], s = src_s[row];
            uint2 ua = *(const uint2*)&g_ABh[d * 512 + c4];
            uint2 ub = *(const uint2*)&g_ABh[s * 512 + 256 + c4];
            __half2 h0 = __hmax2(__hadd2(*(__half2*)&ua.x, *(__half2*)&ub.x), z2);
            __half2 h1 = __hmax2(__hadd2(*(__half2*)&ua.y, *(__half2*)&ub.y), z2);
            uint2 o;
            o.x = *(uint32_t*)&h0;
            o.y = *(uint32_t*)&h1;
            *(uint2*)&h_s[row * KS + c4] = o;
        }
        __syncthreads();

        // Stage 2: fp16 mma [64x256] @ [256x128] via ldmatrix fragments
        float acc[2][4][4];
        #pragma unroll
        for (int mt = 0; mt < 2; ++mt)
            #pragma unroll
            for (int nt = 0; nt < 4; ++nt)
                #pragma unroll
                for (int i = 0; i < 4; ++i) acc[mt][nt][i] = 0.f;

        #pragma unroll 4
        for (int ks = 0; ks < HDIM / 16; ++ks) {
            uint32_t kb = ks * 32;  // k0 * 2 bytes
            uint32_t a[2][4];
            #pragma unroll
            for (int mt = 0; mt < 2; ++mt)
                ldsm_x4(a[mt][0], a[mt][1], a[mt][2], a[mt][3], aBase[mt] + kb);
            uint32_t b[4][2];
            ldsm_x4(b[0][0], b[0][1], b[1][0], b[1][1], bBase[0] + kb);
            ldsm_x4(b[2][0], b[2][1], b[3][0], b[3][1], bBase[1] + kb);
            #pragma unroll
            for (int mt = 0; mt < 2; ++mt)
                #pragma unroll
                for (int nt = 0; nt < 4; ++nt)
                    mma_f16(acc[mt][nt][0], acc[mt][nt][1], acc[mt][nt][2], acc[mt][nt][3],
                            a[mt][0], a[mt][1], a[mt][2], a[mt][3],
                            b[nt][0], b[nt][1]);
        }

        // Epilogue: +b2, predicated positive-only int atomicMax
        #pragma unroll
        for (int mt = 0; mt < 2; ++mt) {
            #pragma unroll
            for (int nt = 0; nt < 4; ++nt) {
                #pragma unroll
                for (int i = 0; i < 4; ++i) {
                    int rowm = wm * 32 + mt * 16 + g + ((i >> 1) * 8);
                    int col  = wn * 32 + nt * 8 + tg * 2 + (i & 1);
                    float v = acc[mt][nt][i] + b2_s[col];
                    if (v > 0.f) {
                        int d = dst_s[rowm];
                        atomicMax(outI + d * COUT + col, __float_as_int(v));
                    }
                }
            }
        }
    }
}

// ---------------------------------------------------------------------------
// Launch
// ---------------------------------------------------------------------------
extern "C" void kernel_launch(void* const* d_in, const int* in_sizes, int n_in,
                              void* d_out, int out_size) {
    const float* x        = (const float*)d_in[0];
    const int*   eiw      = (const int*)d_in[1];
    const float* bn_gamma = (const float*)d_in[2];
    const float* bn_beta  = (const float*)d_in[3];
    const float* bn_mean  = (const float*)d_in[4];
    const float* bn_var   = (const float*)d_in[5];
    const float* W1       = (const float*)d_in[6];
    const float* b1       = (const float*)d_in[7];
    const float* W2       = (const float*)d_in[8];
    const float* b2       = (const float*)d_in[9];
    float* out = (float*)d_out;

    cudaFuncSetAttribute(edge_kernel, cudaFuncAttributeMaxDynamicSharedMemorySize, SMEM_BYTES);

    detect_kernel<<<1, 256>>>(eiw);
    extract_kernel<<<(NEDGES + 255) / 256, 256>>>(eiw);
    prep_kernel<<<1, 512>>>(bn_gamma, bn_beta, bn_mean, bn_var, W1, b1, W2);
    zero_kernel<<<(NNODES * COUT + 511) / 512, 512>>>(out, NNODES * COUT);
    dim3 g1((NNODES + 63) / 64, 512 / 64);
    gemm_nodes_kernel<<<g1, 256>>>(x);
    edge_kernel<<<304, 256, SMEM_BYTES>>>(b2, (int*)d_out);
}